// round 3
// baseline (speedup 1.0000x reference)
#include <cuda_runtime.h>

static constexpr int N = 100000;
static constexpr int E = 1600000;

// ---- device-global scratch (no allocations allowed) ----
__device__ float g_deg[N];
__device__ float g_dinv[N];
__device__ int   g_src[E];
__device__ int   g_dst[E];
__device__ float g_y1[N * 64];
__device__ float g_agg1[N * 64];
__device__ float g_y2[N * 32];
__device__ float g_agg2[N * 32];

// ---- degree: deg[i] = 1 (self loop) + sum of w over edges with dst==i ----
__global__ void k_init_deg() {
    int i = blockIdx.x * blockDim.x + threadIdx.x;
    if (i < N) g_deg[i] = 1.0f;
}

// edge_index arrives from the harness as int32 (int64 is downcast per the
// harness dtype contract). Guard indices so a bad assumption fails
// correctness, not with an illegal access.
__global__ void k_prep_edges(const int* __restrict__ ei,
                             const float* __restrict__ ew) {
    int e = blockIdx.x * blockDim.x + threadIdx.x;
    if (e >= E) return;
    int s = ei[e];
    int d = ei[E + e];
    if ((unsigned)s >= (unsigned)N) s = 0;
    if ((unsigned)d >= (unsigned)N) d = 0;
    g_src[e] = s;
    g_dst[e] = d;
    atomicAdd(&g_deg[d], ew[e]);
}

__global__ void k_dinv() {
    int i = blockIdx.x * blockDim.x + threadIdx.x;
    if (i < N) g_dinv[i] = rsqrtf(g_deg[i]);   // deg >= 1 always
}

// ---- layer-1 GEMM: y1 = dinv * (x @ W1); agg1 initialized to y1 (self-loop term) ----
__global__ void __launch_bounds__(128) k_gemm1(const float* __restrict__ X,
                                               const float* __restrict__ W) {
    constexpr int TX = 16, TY = 8, NPB = 16;   // 16 nodes/block, 2 per thread-row
    __shared__ float Ws[64 * 64];
    __shared__ float Xs[NPB][68];              // pad: stride 68 floats (16B-aligned rows)
    int tid = threadIdx.y * TX + threadIdx.x;

    {   // stage W1 (64x64) in smem
        const float4* Wg = (const float4*)W;
        float4* Ws4 = (float4*)Ws;
        #pragma unroll
        for (int i = tid; i < 64 * 64 / 4; i += 128) Ws4[i] = Wg[i];
    }
    int nb = blockIdx.x * NPB;                 // N % 16 == 0
    for (int i = tid; i < NPB * 16; i += 128) {
        int node = i >> 4, k4 = i & 15;
        float4 v = ((const float4*)(X + (nb + node) * 64))[k4];
        *((float4*)&Xs[node][k4 * 4]) = v;
    }
    __syncthreads();

    int tx = threadIdx.x, ty = threadIdx.y;
    float4 a0 = make_float4(0, 0, 0, 0), a1 = make_float4(0, 0, 0, 0);
    #pragma unroll
    for (int k = 0; k < 64; k++) {
        float4 w4 = *((const float4*)&Ws[k * 64 + tx * 4]);
        float x0 = Xs[ty][k], x1 = Xs[ty + TY][k];
        a0.x = fmaf(x0, w4.x, a0.x); a0.y = fmaf(x0, w4.y, a0.y);
        a0.z = fmaf(x0, w4.z, a0.z); a0.w = fmaf(x0, w4.w, a0.w);
        a1.x = fmaf(x1, w4.x, a1.x); a1.y = fmaf(x1, w4.y, a1.y);
        a1.z = fmaf(x1, w4.z, a1.z); a1.w = fmaf(x1, w4.w, a1.w);
    }
    int n0 = nb + ty, n1 = nb + ty + TY;
    float s0 = g_dinv[n0], s1 = g_dinv[n1];
    a0.x *= s0; a0.y *= s0; a0.z *= s0; a0.w *= s0;
    a1.x *= s1; a1.y *= s1; a1.z *= s1; a1.w *= s1;
    *((float4*)&g_y1[n0 * 64 + tx * 4])   = a0;
    *((float4*)&g_agg1[n0 * 64 + tx * 4]) = a0;
    *((float4*)&g_y1[n1 * 64 + tx * 4])   = a1;
    *((float4*)&g_agg1[n1 * 64 + tx * 4]) = a1;
}

// ---- layer-1 scatter: agg1[d] += w_e * y1[s], warp per edge, float2 per lane ----
__global__ void __launch_bounds__(256) k_scatter1(const float* __restrict__ ew) {
    int t = blockIdx.x * blockDim.x + threadIdx.x;
    int e = t >> 5;
    if (e >= E) return;
    int lane = t & 31;
    int s = g_src[e], d = g_dst[e];
    float w = ew[e];
    float2 v = __ldg((const float2*)&g_y1[s * 64 + lane * 2]);
    float* ap = &g_agg1[d * 64 + lane * 2];
    atomicAdd(ap,     w * v.x);
    atomicAdd(ap + 1, w * v.y);
}

// ---- fused: h = relu(dinv*agg1 + b1); y2 = dinv * (h @ W2); agg2 = y2 ----
__global__ void __launch_bounds__(128) k_layer2(const float* __restrict__ W2,
                                                const float* __restrict__ b1) {
    constexpr int TX = 8, TY = 16, NPB = 32;
    __shared__ float Ws[64 * 32];
    __shared__ float Xs[NPB][68];
    int tid = threadIdx.y * TX + threadIdx.x;

    {
        const float4* Wg = (const float4*)W2;
        float4* Ws4 = (float4*)Ws;
        #pragma unroll
        for (int i = tid; i < 64 * 32 / 4; i += 128) Ws4[i] = Wg[i];
    }
    int nb = blockIdx.x * NPB;                 // N % 32 == 0
    for (int i = tid; i < NPB * 16; i += 128) {
        int node = i >> 4, k4 = i & 15;
        int n = nb + node;
        float4 a = ((const float4*)&g_agg1[n * 64])[k4];
        float4 b = ((const float4*)b1)[k4];
        float sc = g_dinv[n];
        float4 h;
        h.x = fmaxf(fmaf(sc, a.x, b.x), 0.0f);
        h.y = fmaxf(fmaf(sc, a.y, b.y), 0.0f);
        h.z = fmaxf(fmaf(sc, a.z, b.z), 0.0f);
        h.w = fmaxf(fmaf(sc, a.w, b.w), 0.0f);
        *((float4*)&Xs[node][k4 * 4]) = h;
    }
    __syncthreads();

    int tx = threadIdx.x, ty = threadIdx.y;
    float4 a0 = make_float4(0, 0, 0, 0), a1 = make_float4(0, 0, 0, 0);
    #pragma unroll
    for (int k = 0; k < 64; k++) {
        float4 w4 = *((const float4*)&Ws[k * 32 + tx * 4]);
        float x0 = Xs[ty][k], x1 = Xs[ty + TY][k];
        a0.x = fmaf(x0, w4.x, a0.x); a0.y = fmaf(x0, w4.y, a0.y);
        a0.z = fmaf(x0, w4.z, a0.z); a0.w = fmaf(x0, w4.w, a0.w);
        a1.x = fmaf(x1, w4.x, a1.x); a1.y = fmaf(x1, w4.y, a1.y);
        a1.z = fmaf(x1, w4.z, a1.z); a1.w = fmaf(x1, w4.w, a1.w);
    }
    int n0 = nb + ty, n1 = nb + ty + TY;
    float s0 = g_dinv[n0], s1 = g_dinv[n1];
    a0.x *= s0; a0.y *= s0; a0.z *= s0; a0.w *= s0;
    a1.x *= s1; a1.y *= s1; a1.z *= s1; a1.w *= s1;
    *((float4*)&g_y2[n0 * 32 + tx * 4])   = a0;
    *((float4*)&g_agg2[n0 * 32 + tx * 4]) = a0;
    *((float4*)&g_y2[n1 * 32 + tx * 4])   = a1;
    *((float4*)&g_agg2[n1 * 32 + tx * 4]) = a1;
}

// ---- layer-2 scatter: agg2[d] += w_e * y2[s], warp per edge, 1 float per lane ----
__global__ void __launch_bounds__(256) k_scatter2(const float* __restrict__ ew) {
    int t = blockIdx.x * blockDim.x + threadIdx.x;
    int e = t >> 5;
    if (e >= E) return;
    int lane = t & 31;
    int s = g_src[e], d = g_dst[e];
    float w = ew[e];
    float v = __ldg(&g_y2[s * 32 + lane]);
    atomicAdd(&g_agg2[d * 32 + lane], w * v);
}

// ---- epilogue: out = dinv * agg2 + b2 ----
__global__ void k_finish(const float* __restrict__ b2, float* __restrict__ out) {
    int i = blockIdx.x * blockDim.x + threadIdx.x;
    if (i >= N * 32) return;
    int n = i >> 5, c = i & 31;
    out[i] = fmaf(g_dinv[n], g_agg2[i], b2[c]);
}

extern "C" void kernel_launch(void* const* d_in, const int* in_sizes, int n_in,
                              void* d_out, int out_size) {
    const float* x  = (const float*)d_in[0];
    const int*   ei = (const int*)d_in[1];     // edge_index as int32 (harness downcasts int64)
    const float* ew = (const float*)d_in[2];
    const float* W1 = (const float*)d_in[3];
    const float* b1 = (const float*)d_in[4];
    const float* W2 = (const float*)d_in[5];
    const float* b2 = (const float*)d_in[6];
    float* out = (float*)d_out;

    k_init_deg  <<<(N + 255) / 256, 256>>>();
    k_prep_edges<<<(E + 255) / 256, 256>>>(ei, ew);
    k_dinv      <<<(N + 255) / 256, 256>>>();
    k_gemm1     <<<N / 16, dim3(16, 8)>>>(x, W1);
    k_scatter1  <<<(E * 32) / 256, 256>>>(ew);     // 200000 blocks, warp/edge
    k_layer2    <<<N / 32, dim3(8, 16)>>>(W2, b1);
    k_scatter2  <<<(E * 32) / 256, 256>>>(ew);
    k_finish    <<<(N * 32 + 255) / 256, 256>>>(b2, out);
}

// round 4
// speedup vs baseline: 2.2890x; 2.2890x over previous
#include <cuda_runtime.h>

static constexpr int N = 100000;
static constexpr int E = 1600000;
static constexpr int SCAN_B = 512;
static constexpr int NB_SCAN = (N + SCAN_B - 1) / SCAN_B;   // 196

// ---- device-global scratch ----
__device__ float g_deg[N];
__device__ float g_dinv[N];
__device__ int   g_cnt[N];      // in-degree counts
__device__ int   g_scan[N];     // block-local inclusive scan of cnt
__device__ int   g_rs[N];       // CSR row start (exclusive prefix)
__device__ int   g_cur[N];      // reorder cursors
__device__ int   g_bsum[NB_SCAN];
__device__ int   g_boff[NB_SCAN];
__device__ int2  g_edge[E];     // bucketed edges: {src, w as bits}
__device__ float g_y1[N * 64];
__device__ float g_h [N * 64];
__device__ float g_y2[N * 32];

// ---- init: deg=1 (self loop), cnt=0 ----
__global__ void k_init() {
    int i = blockIdx.x * blockDim.x + threadIdx.x;
    if (i < N) { g_deg[i] = 1.0f; g_cnt[i] = 0; }
}

// ---- count + weighted degree ----
__global__ void k_prep(const int* __restrict__ ei, const float* __restrict__ ew) {
    int e = blockIdx.x * blockDim.x + threadIdx.x;
    if (e >= E) return;
    int d = ei[E + e];
    if ((unsigned)d >= (unsigned)N) d = 0;
    atomicAdd(&g_deg[d], ew[e]);
    atomicAdd(&g_cnt[d], 1);
}

// ---- scan stage 1: per-block inclusive scan of counts ----
__global__ void k_scan_block() {
    __shared__ int sh[SCAN_B];
    int t = threadIdx.x;
    int g = blockIdx.x * SCAN_B + t;
    int v = (g < N) ? g_cnt[g] : 0;
    sh[t] = v; __syncthreads();
    #pragma unroll
    for (int off = 1; off < SCAN_B; off <<= 1) {
        int add = (t >= off) ? sh[t - off] : 0;
        __syncthreads();
        sh[t] += add;
        __syncthreads();
    }
    if (g < N) g_scan[g] = sh[t];
    if (t == SCAN_B - 1) g_bsum[blockIdx.x] = sh[t];
}

// ---- scan stage 2: exclusive scan of block sums (single block) ----
__global__ void k_scan_bsum() {
    __shared__ int sh[256];
    int t = threadIdx.x;
    int v = (t < NB_SCAN) ? g_bsum[t] : 0;
    sh[t] = v; __syncthreads();
    #pragma unroll
    for (int off = 1; off < 256; off <<= 1) {
        int add = (t >= off) ? sh[t - off] : 0;
        __syncthreads();
        sh[t] += add;
        __syncthreads();
    }
    if (t < NB_SCAN) g_boff[t] = sh[t] - v;   // exclusive
}

// ---- scan stage 3: row starts, cursors, dinv ----
__global__ void k_scan_fix() {
    int i = blockIdx.x * blockDim.x + threadIdx.x;
    if (i >= N) return;
    int incl = g_scan[i] + g_boff[i / SCAN_B];
    int start = incl - g_cnt[i];
    g_rs[i]  = start;
    g_cur[i] = start;
    g_dinv[i] = rsqrtf(g_deg[i]);
}

// ---- bucket edges by destination ----
__global__ void k_reorder(const int* __restrict__ ei, const float* __restrict__ ew) {
    int e = blockIdx.x * blockDim.x + threadIdx.x;
    if (e >= E) return;
    int s = ei[e];
    int d = ei[E + e];
    if ((unsigned)s >= (unsigned)N) s = 0;
    if ((unsigned)d >= (unsigned)N) d = 0;
    int pos = atomicAdd(&g_cur[d], 1);
    g_edge[pos] = make_int2(s, __float_as_int(ew[e]));
}

// ---- layer-1 GEMM: y1 = dinv * (x @ W1). 4 nodes/thread ----
__global__ void __launch_bounds__(128) k_gemm1(const float* __restrict__ X,
                                               const float* __restrict__ W) {
    constexpr int TX = 16, NPB = 32;
    __shared__ float Ws[64 * 64];
    __shared__ float Xs[NPB][68];
    int tid = threadIdx.y * TX + threadIdx.x;

    {
        const float4* Wg = (const float4*)W;
        float4* Ws4 = (float4*)Ws;
        #pragma unroll
        for (int i = tid; i < 64 * 64 / 4; i += 128) Ws4[i] = Wg[i];
    }
    int nb = blockIdx.x * NPB;                 // N % 32 == 0
    #pragma unroll
    for (int i = tid; i < NPB * 16; i += 128) {
        int node = i >> 4, k4 = i & 15;
        *((float4*)&Xs[node][k4 * 4]) = ((const float4*)(X + (nb + node) * 64))[k4];
    }
    __syncthreads();

    int tx = threadIdx.x, ty = threadIdx.y;    // ty in 0..7
    float4 a0 = {0,0,0,0}, a1 = {0,0,0,0}, a2 = {0,0,0,0}, a3 = {0,0,0,0};
    #pragma unroll
    for (int k = 0; k < 64; k++) {
        float4 w4 = *((const float4*)&Ws[k * 64 + tx * 4]);
        float x0 = Xs[ty][k], x1 = Xs[ty + 8][k], x2 = Xs[ty + 16][k], x3 = Xs[ty + 24][k];
        a0.x = fmaf(x0, w4.x, a0.x); a0.y = fmaf(x0, w4.y, a0.y);
        a0.z = fmaf(x0, w4.z, a0.z); a0.w = fmaf(x0, w4.w, a0.w);
        a1.x = fmaf(x1, w4.x, a1.x); a1.y = fmaf(x1, w4.y, a1.y);
        a1.z = fmaf(x1, w4.z, a1.z); a1.w = fmaf(x1, w4.w, a1.w);
        a2.x = fmaf(x2, w4.x, a2.x); a2.y = fmaf(x2, w4.y, a2.y);
        a2.z = fmaf(x2, w4.z, a2.z); a2.w = fmaf(x2, w4.w, a2.w);
        a3.x = fmaf(x3, w4.x, a3.x); a3.y = fmaf(x3, w4.y, a3.y);
        a3.z = fmaf(x3, w4.z, a3.z); a3.w = fmaf(x3, w4.w, a3.w);
    }
    #pragma unroll
    for (int m = 0; m < 4; m++) {
        int n = nb + ty + 8 * m;
        float sc = g_dinv[n];
        float4 a = (m == 0) ? a0 : (m == 1) ? a1 : (m == 2) ? a2 : a3;
        a.x *= sc; a.y *= sc; a.z *= sc; a.w *= sc;
        *((float4*)&g_y1[n * 64 + tx * 4]) = a;
    }
}

// ---- layer-1 aggregate (warp per node): h = relu(dinv*(y1[d] + sum w*y1[s]) + b1) ----
__global__ void __launch_bounds__(256) k_agg1(const float* __restrict__ b1) {
    int warp = (blockIdx.x * 256 + threadIdx.x) >> 5;
    if (warp >= N) return;
    int lane = threadIdx.x & 31;
    int d = warp;
    int beg = g_rs[d], end = beg + g_cnt[d];
    float2 acc = *(const float2*)&g_y1[d * 64 + lane * 2];   // self loop
    int j = beg;
    for (; j + 3 < end; j += 4) {
        int2 e0 = __ldg(&g_edge[j]),     e1 = __ldg(&g_edge[j + 1]);
        int2 e2 = __ldg(&g_edge[j + 2]), e3 = __ldg(&g_edge[j + 3]);
        float2 v0 = __ldg((const float2*)&g_y1[e0.x * 64 + lane * 2]);
        float2 v1 = __ldg((const float2*)&g_y1[e1.x * 64 + lane * 2]);
        float2 v2 = __ldg((const float2*)&g_y1[e2.x * 64 + lane * 2]);
        float2 v3 = __ldg((const float2*)&g_y1[e3.x * 64 + lane * 2]);
        float w0 = __int_as_float(e0.y), w1 = __int_as_float(e1.y);
        float w2 = __int_as_float(e2.y), w3 = __int_as_float(e3.y);
        acc.x = fmaf(w0, v0.x, acc.x); acc.y = fmaf(w0, v0.y, acc.y);
        acc.x = fmaf(w1, v1.x, acc.x); acc.y = fmaf(w1, v1.y, acc.y);
        acc.x = fmaf(w2, v2.x, acc.x); acc.y = fmaf(w2, v2.y, acc.y);
        acc.x = fmaf(w3, v3.x, acc.x); acc.y = fmaf(w3, v3.y, acc.y);
    }
    for (; j < end; j++) {
        int2 e = __ldg(&g_edge[j]);
        float w = __int_as_float(e.y);
        float2 v = __ldg((const float2*)&g_y1[e.x * 64 + lane * 2]);
        acc.x = fmaf(w, v.x, acc.x); acc.y = fmaf(w, v.y, acc.y);
    }
    float di = g_dinv[d];
    float bx = b1[lane * 2], by = b1[lane * 2 + 1];
    float2 h;
    h.x = fmaxf(fmaf(di, acc.x, bx), 0.0f);
    h.y = fmaxf(fmaf(di, acc.y, by), 0.0f);
    *((float2*)&g_h[d * 64 + lane * 2]) = h;
}

// ---- layer-2 GEMM: y2 = dinv * (h @ W2) ----
__global__ void __launch_bounds__(128) k_gemm2(const float* __restrict__ W2) {
    constexpr int TX = 8, TY = 16, NPB = 32;
    __shared__ float Ws[64 * 32];
    __shared__ float Xs[NPB][68];
    int tid = threadIdx.y * TX + threadIdx.x;

    {
        const float4* Wg = (const float4*)W2;
        float4* Ws4 = (float4*)Ws;
        #pragma unroll
        for (int i = tid; i < 64 * 32 / 4; i += 128) Ws4[i] = Wg[i];
    }
    int nb = blockIdx.x * NPB;                 // N % 32 == 0
    #pragma unroll
    for (int i = tid; i < NPB * 16; i += 128) {
        int node = i >> 4, k4 = i & 15;
        *((float4*)&Xs[node][k4 * 4]) = ((const float4*)&g_h[(nb + node) * 64])[k4];
    }
    __syncthreads();

    int tx = threadIdx.x, ty = threadIdx.y;
    float4 a0 = {0,0,0,0}, a1 = {0,0,0,0};
    #pragma unroll
    for (int k = 0; k < 64; k++) {
        float4 w4 = *((const float4*)&Ws[k * 32 + tx * 4]);
        float x0 = Xs[ty][k], x1 = Xs[ty + TY][k];
        a0.x = fmaf(x0, w4.x, a0.x); a0.y = fmaf(x0, w4.y, a0.y);
        a0.z = fmaf(x0, w4.z, a0.z); a0.w = fmaf(x0, w4.w, a0.w);
        a1.x = fmaf(x1, w4.x, a1.x); a1.y = fmaf(x1, w4.y, a1.y);
        a1.z = fmaf(x1, w4.z, a1.z); a1.w = fmaf(x1, w4.w, a1.w);
    }
    int n0 = nb + ty, n1 = nb + ty + TY;
    float s0 = g_dinv[n0], s1 = g_dinv[n1];
    a0.x *= s0; a0.y *= s0; a0.z *= s0; a0.w *= s0;
    a1.x *= s1; a1.y *= s1; a1.z *= s1; a1.w *= s1;
    *((float4*)&g_y2[n0 * 32 + tx * 4]) = a0;
    *((float4*)&g_y2[n1 * 32 + tx * 4]) = a1;
}

// ---- layer-2 aggregate + epilogue: out = dinv*(y2[d] + sum w*y2[s]) + b2 ----
__global__ void __launch_bounds__(256) k_agg2(const float* __restrict__ b2,
                                              float* __restrict__ out) {
    int warp = (blockIdx.x * 256 + threadIdx.x) >> 5;
    if (warp >= N) return;
    int lane = threadIdx.x & 31;
    int d = warp;
    int beg = g_rs[d], end = beg + g_cnt[d];
    float acc = g_y2[d * 32 + lane];           // self loop
    int j = beg;
    for (; j + 3 < end; j += 4) {
        int2 e0 = __ldg(&g_edge[j]),     e1 = __ldg(&g_edge[j + 1]);
        int2 e2 = __ldg(&g_edge[j + 2]), e3 = __ldg(&g_edge[j + 3]);
        float v0 = __ldg(&g_y2[e0.x * 32 + lane]);
        float v1 = __ldg(&g_y2[e1.x * 32 + lane]);
        float v2 = __ldg(&g_y2[e2.x * 32 + lane]);
        float v3 = __ldg(&g_y2[e3.x * 32 + lane]);
        acc = fmaf(__int_as_float(e0.y), v0, acc);
        acc = fmaf(__int_as_float(e1.y), v1, acc);
        acc = fmaf(__int_as_float(e2.y), v2, acc);
        acc = fmaf(__int_as_float(e3.y), v3, acc);
    }
    for (; j < end; j++) {
        int2 e = __ldg(&g_edge[j]);
        acc = fmaf(__int_as_float(e.y), __ldg(&g_y2[e.x * 32 + lane]), acc);
    }
    out[d * 32 + lane] = fmaf(g_dinv[d], acc, b2[lane]);
}

extern "C" void kernel_launch(void* const* d_in, const int* in_sizes, int n_in,
                              void* d_out, int out_size) {
    const float* x  = (const float*)d_in[0];
    const int*   ei = (const int*)d_in[1];     // edge_index as int32
    const float* ew = (const float*)d_in[2];
    const float* W1 = (const float*)d_in[3];
    const float* b1 = (const float*)d_in[4];
    const float* W2 = (const float*)d_in[5];
    const float* b2 = (const float*)d_in[6];
    float* out = (float*)d_out;

    k_init      <<<(N + 255) / 256, 256>>>();
    k_prep      <<<(E + 255) / 256, 256>>>(ei, ew);
    k_scan_block<<<NB_SCAN, SCAN_B>>>();
    k_scan_bsum <<<1, 256>>>();
    k_scan_fix  <<<(N + 255) / 256, 256>>>();
    k_reorder   <<<(E + 255) / 256, 256>>>(ei, ew);
    k_gemm1     <<<N / 32, dim3(16, 8)>>>(x, W1);
    k_agg1      <<<(N * 32 + 255) / 256, 256>>>(b1);
    k_gemm2     <<<N / 32, dim3(8, 16)>>>(W2);
    k_agg2      <<<(N * 32 + 255) / 256, 256>>>(b2, out);
}